// round 4
// baseline (speedup 1.0000x reference)
#include <cuda_runtime.h>
#include <cuda_bf16.h>
#include <math.h>

#define BB    128
#define DD    128
#define NPTS  100000
#define KTOT  8194
#define NEGK  8192
#define INV_TAU (1.0f/0.07f)

// bf16 quantized copies of the (stop-gradient) memory banks.
// 2 x 25.6MB static device scratch -> whole gather working set is L2-resident.
__device__ __nv_bfloat16 g_m0h[NPTS * DD];
__device__ __nv_bfloat16 g_m1h[NPTS * DD];

// per-(CTA) partial statistics (2 CTAs per batch row) and direct logits
__device__ float g_partial[2 * BB][16];
__device__ float g_direct[BB][6];

// stat id (0..7 within a pair):
// 0: s1x (z=x, w=1)   1: s1y (z=y, w=1)   2: s3x (z=x/3, w=1)  3: wxx
// 4: wxy              5: s3y (z=y/3,w=1)  6: wyy               7: wyx
__constant__ float c_ZU[8] = {1.f, 0.f, 1.f/3.f, 1.f/3.f, 1.f/3.f, 0.f,     0.f,     0.f    };
__constant__ float c_ZV[8] = {0.f, 1.f, 0.f,     0.f,     0.f,     1.f/3.f, 1.f/3.f, 1.f/3.f};
__constant__ float c_WU[8] = {0.f, 0.f, 0.f,     1.f/3.f, 0.f,     0.f,     0.f,     1.f/3.f};
__constant__ float c_WV[8] = {0.f, 0.f, 0.f,     0.f,     1.f/3.f, 0.f,     1.f/3.f, 0.f    };
__constant__ float c_WC[8] = {1.f, 1.f, 1.f,     0.f,     0.f,     1.f,     0.f,     0.f    };

// stream/event resources created at static-init time (host-side only).
static cudaStream_t g_s2;
static cudaEvent_t  g_ev0, g_ev1;
struct HxInitStreams {
    HxInitStreams() {
        cudaStreamCreateWithFlags(&g_s2, cudaStreamNonBlocking);
        cudaEventCreateWithFlags(&g_ev0, cudaEventDisableTiming);
        cudaEventCreateWithFlags(&g_ev1, cudaEventDisableTiming);
    }
};
static HxInitStreams g_hx_init;

// ---------------------------------------------------------------------------
// fp32 -> bf16 conversion of both mem banks. 8 elems per thread-iteration.
__global__ __launch_bounds__(256) void convert_kernel(
    const float4* __restrict__ m0, const float4* __restrict__ m1)
{
    const int n = NPTS * DD / 8;              // 1.6M chunks of 8 floats
    const int stride = gridDim.x * blockDim.x;
    for (int i = blockIdx.x * blockDim.x + threadIdx.x; i < n; i += stride) {
        float4 a = m0[2*i], b = m0[2*i + 1];
        uint4 o;
        __nv_bfloat162 h;
        h.x = __float2bfloat16_rn(a.x); h.y = __float2bfloat16_rn(a.y); o.x = *(unsigned*)&h;
        h.x = __float2bfloat16_rn(a.z); h.y = __float2bfloat16_rn(a.w); o.y = *(unsigned*)&h;
        h.x = __float2bfloat16_rn(b.x); h.y = __float2bfloat16_rn(b.y); o.z = *(unsigned*)&h;
        h.x = __float2bfloat16_rn(b.z); h.y = __float2bfloat16_rn(b.w); o.w = *(unsigned*)&h;
        ((uint4*)g_m0h)[i] = o;

        a = m1[2*i]; b = m1[2*i + 1];
        h.x = __float2bfloat16_rn(a.x); h.y = __float2bfloat16_rn(a.y); o.x = *(unsigned*)&h;
        h.x = __float2bfloat16_rn(a.z); h.y = __float2bfloat16_rn(a.w); o.y = *(unsigned*)&h;
        h.x = __float2bfloat16_rn(b.x); h.y = __float2bfloat16_rn(b.y); o.z = *(unsigned*)&h;
        h.x = __float2bfloat16_rn(b.z); h.y = __float2bfloat16_rn(b.w); o.w = *(unsigned*)&h;
        ((uint4*)g_m1h)[i] = o;
    }
}

__device__ __forceinline__ float dot8_bf16(uint4 A, float4 ea, float4 eb) {
    float2 f;
    float s;
    f = __bfloat1622float2(*(__nv_bfloat162*)&A.x); s  = f.x*ea.x + f.y*ea.y;
    f = __bfloat1622float2(*(__nv_bfloat162*)&A.y); s += f.x*ea.z + f.y*ea.w;
    f = __bfloat1622float2(*(__nv_bfloat162*)&A.z); s += f.x*eb.x + f.y*eb.y;
    f = __bfloat1622float2(*(__nv_bfloat162*)&A.w); s += f.x*eb.z + f.y*eb.w;
    return s;
}

// ---------------------------------------------------------------------------
// 2 CTAs per batch row b (half = blockIdx&1), 512 threads each -> 2 CTAs/SM.
// 16-lane groups own one k per iteration; lane `pos` covers elems
// [pos*8, pos*8+8) so each group's bf16 LDG.128 is 256B contiguous.
__global__ __launch_bounds__(512, 2) void gather_stats_kernel(
    const float* __restrict__ emb0, const float* __restrict__ emb1,
    const int* __restrict__ pos_idx, const int* __restrict__ neg_idx)
{
    const int b    = blockIdx.x >> 1;
    const int half = blockIdx.x & 1;
    const int tid = threadIdx.x;
    const int w   = tid >> 5;       // warp 0..15
    const int l   = tid & 31;
    const int grp = l >> 4;
    const int pos = l & 15;         // lane within group == stat id == D-seg
    const int m   = pos & 7;
    const bool isB = (pos >= 8);

    const float4* e0p = (const float4*)(emb0 + b * DD);
    const float4* e1p = (const float4*)(emb1 + b * DD);
    const float4 e0a = e0p[2*pos], e0b = e0p[2*pos + 1];
    const float4 e1a = e1p[2*pos], e1b = e1p[2*pos + 1];

    const float czu = c_ZU[m], czv = c_ZV[m];
    const float cwu = c_WU[m], cwv = c_WV[m], cwc = c_WC[m];

    const int* prow = pos_idx + b * 2;
    const int* nrow = neg_idx + b * NEGK;

    float acc = 0.f;
    const int kbase = (w << 1) + grp + (half << 5);   // 0..63

    #pragma unroll 2
    for (int it = 0; it < 129; ++it) {
        const int k = it * 64 + kbase;
        if (k < KTOT) {                               // warp-uniform branch
            const int idx = (k < 2) ? prow[k] : nrow[k - 2];
            // bf16 row = 256B = 16 uint4
            const uint4 A = ((const uint4*)g_m0h)[idx * 16 + pos];
            const uint4 Bv = ((const uint4*)g_m1h)[idx * 16 + pos];

            float pu = dot8_bf16(A,  e1a, e1b);   // m0 . e1
            float pv = dot8_bf16(Bv, e0a, e0b);   // m1 . e0
            float pp = dot8_bf16(A,  e0a, e0b);   // m0 . e0
            float pq = dot8_bf16(Bv, e1a, e1b);   // m1 . e1

            #pragma unroll
            for (int d = 1; d < 16; d <<= 1) {
                pu += __shfl_xor_sync(0xffffffffu, pu, d);
                pv += __shfl_xor_sync(0xffffffffu, pv, d);
                pp += __shfl_xor_sync(0xffffffffu, pp, d);
                pq += __shfl_xor_sync(0xffffffffu, pq, d);
            }
            const float u = pu * INV_TAU, v = pv * INV_TAU;
            const float p = pp * INV_TAU, q = pq * INV_TAU;

            if (pos == 0 && k < 2) {   // half 0, warp 0, iter 0
                g_direct[b][k]     = u;
                g_direct[b][2 + k] = v;
                if (k == 1) { g_direct[b][4] = p; g_direct[b][5] = q; }
            }

            const float x = isB ? p : u;
            const float y = isB ? q : v;
            if (!isB || k >= 1)
                acc += __expf(czu * x + czv * y) * (cwu * x + cwv * y + cwc);
        }
    }

    acc += __shfl_xor_sync(0xffffffffu, acc, 16);   // combine warp's 2 groups

    __shared__ float sm[16][16];
    if (l < 16) sm[l][w] = acc;
    __syncthreads();
    if (tid < 16) {
        float s = 0.f;
        #pragma unroll
        for (int ww = 0; ww < 16; ++ww) s += sm[tid][ww];
        g_partial[blockIdx.x][tid] = s;
    }
}

// ---------------------------------------------------------------------------
// Streaming copy of mem0|mem1 into out (evict-first both sides).
__global__ __launch_bounds__(256) void copy_mems_kernel(
    const float4* __restrict__ m0, const float4* __restrict__ m1,
    float4* __restrict__ dst)
{
    const int n = NPTS * DD / 4;
    const int stride = gridDim.x * blockDim.x;
    for (int i = blockIdx.x * blockDim.x + threadIdx.x; i < n; i += stride) {
        __stcs(dst + i,     __ldcs(m0 + i));
        __stcs(dst + n + i, __ldcs(m1 + i));
    }
}

// one warp per (b, net): momentum update + renorm + scatter (exact fp32).
__global__ void update_rows_kernel(
    const float* __restrict__ emb0, const float* __restrict__ emb1,
    const float* __restrict__ mem0, const float* __restrict__ mem1,
    const int* __restrict__ pos_idx, float* __restrict__ out)
{
    const int g = blockIdx.x * (blockDim.x >> 5) + (threadIdx.x >> 5);
    const int l = threadIdx.x & 31;
    if (g >= 2 * BB) return;
    const int b = g >> 1, net = g & 1;
    const float* mem = net ? mem1 : mem0;
    const float* emb = net ? emb1 : emb0;
    const int p0 = pos_idx[b * 2];

    float4 mv = ((const float4*)(mem + (size_t)p0 * DD))[l];
    float4 ev = ((const float4*)(emb + (size_t)b  * DD))[l];
    float4 u;
    u.x = 0.5f * (mv.x + ev.x);  u.y = 0.5f * (mv.y + ev.y);
    u.z = 0.5f * (mv.z + ev.z);  u.w = 0.5f * (mv.w + ev.w);
    float ss = u.x*u.x + u.y*u.y + u.z*u.z + u.w*u.w;
    #pragma unroll
    for (int d = 1; d < 32; d <<= 1) ss += __shfl_xor_sync(0xffffffffu, ss, d);
    const float r = 1.0f / sqrtf(ss);
    u.x *= r; u.y *= r; u.z *= r; u.w *= r;

    float* dst = out + 4 + (size_t)net * NPTS * DD + (size_t)p0 * DD;
    ((float4*)dst)[l] = u;
}

// ---------------------------------------------------------------------------
__global__ void finalize_kernel(float* __restrict__ out)
{
    const int b = threadIdx.x;   // 128 threads
    float st[16];
    #pragma unroll
    for (int i = 0; i < 16; ++i)
        st[i] = g_partial[2*b][i] + g_partial[2*b + 1][i];
    const float* dv = g_direct[b];

    const float s1u = st[0],  s1v = st[1],  s3u = st[2],  wuu = st[3];
    const float wuv = st[4],  s3v = st[5],  wvv = st[6],  wvu = st[7];
    const float s1p = st[8],  s1q = st[9],  s3p = st[10], wpp = st[11];
    const float wpq = st[12], s3q = st[13], wqq = st[14], wqp = st[15];
    const float u0 = dv[0], u1 = dv[1], v0 = dv[2], v1 = dv[3];
    const float p1 = dv[4], q1 = dv[5];

    const float icl_b = -((u0 + u1) * 0.5f - logf(s1u))
                        -((v0 + v1) * 0.5f - logf(s1v));
    const float vcl_b = -(p1 - logf(s1p)) - (q1 - logf(s1q));
    const float l3u = logf(s3u), l3v = logf(s3v);
    const float l3p = logf(s3p), l3q = logf(s3q);
    const float sicl_b = ((wvv - wvu) / s3v - l3v + l3u)
                       + ((wuu - wuv) / s3u - l3u + l3v);
    const float svcl_b = ((wqq - wqp) / s3q - l3q + l3p)
                       + ((wpp - wpq) / s3p - l3p + l3q);

    __shared__ float red[4][4];
    float vals[4] = {vcl_b, svcl_b, icl_b, sicl_b};
    const int w = b >> 5, l = b & 31;
    #pragma unroll
    for (int i = 0; i < 4; ++i) {
        float s = vals[i];
        #pragma unroll
        for (int d = 1; d < 32; d <<= 1) s += __shfl_xor_sync(0xffffffffu, s, d);
        if (l == 0) red[i][w] = s;
    }
    __syncthreads();
    if (b == 0) {
        out[0] = (red[0][0] + red[0][1] + red[0][2] + red[0][3]) * (1.0f / BB);
        out[1] = (red[1][0] + red[1][1] + red[1][2] + red[1][3]) * (9.0f / BB);
        out[2] = (red[2][0] + red[2][1] + red[2][2] + red[2][3]) * (1.0f / BB);
        out[3] = (red[3][0] + red[3][1] + red[3][2] + red[3][3]) * (9.0f / BB);
    }
}

extern "C" void kernel_launch(void* const* d_in, const int* in_sizes, int n_in,
                              void* d_out, int out_size)
{
    const float* emb0    = (const float*)d_in[0];
    const float* emb1    = (const float*)d_in[1];
    const float* mem0    = (const float*)d_in[2];
    const float* mem1    = (const float*)d_in[3];
    const int*   pos_idx = (const int*)d_in[4];
    const int*   neg_idx = (const int*)d_in[5];
    float* out = (float*)d_out;

    cudaEventRecord(g_ev0, 0);
    cudaStreamWaitEvent(g_s2, g_ev0, 0);

    // branch B (independent of gather): fp32 copy + exact scatter update
    copy_mems_kernel<<<2048, 256, 0, g_s2>>>(
        (const float4*)mem0, (const float4*)mem1, (float4*)(out + 4));
    update_rows_kernel<<<8, 1024, 0, g_s2>>>(emb0, emb1, mem0, mem1, pos_idx, out);
    cudaEventRecord(g_ev1, g_s2);

    // branch A (critical path): bf16 convert -> L2-resident gather -> finalize
    convert_kernel<<<2048, 256>>>((const float4*)mem0, (const float4*)mem1);
    gather_stats_kernel<<<2 * BB, 512>>>(emb0, emb1, pos_idx, neg_idx);
    finalize_kernel<<<1, 128>>>(out);

    cudaStreamWaitEvent(0, g_ev1, 0);
}

// round 5
// speedup vs baseline: 1.5504x; 1.5504x over previous
#include <cuda_runtime.h>
#include <math.h>

#define BB    128
#define DD    128
#define NPTS  100000
#define KTOT  8194
#define NEGK  8192
#define INV_TAU (1.0f/0.07f)

// per-row streaming statistics (16 per row) and direct logit values (6 per row)
__device__ float g_rowstats[BB][16];
__device__ float g_direct[BB][6];

// stat id (0..7 within a pair):
// 0: s1x (z=x, w=1)   1: s1y (z=y, w=1)   2: s3x (z=x/3, w=1)  3: wxx
// 4: wxy              5: s3y (z=y/3,w=1)  6: wyy               7: wyx
__constant__ float c_ZU[8] = {1.f, 0.f, 1.f/3.f, 1.f/3.f, 1.f/3.f, 0.f,     0.f,     0.f    };
__constant__ float c_ZV[8] = {0.f, 1.f, 0.f,     0.f,     0.f,     1.f/3.f, 1.f/3.f, 1.f/3.f};
__constant__ float c_WU[8] = {0.f, 0.f, 0.f,     1.f/3.f, 0.f,     0.f,     0.f,     1.f/3.f};
__constant__ float c_WV[8] = {0.f, 0.f, 0.f,     0.f,     1.f/3.f, 0.f,     1.f/3.f, 0.f    };
__constant__ float c_WC[8] = {1.f, 1.f, 1.f,     0.f,     0.f,     1.f,     0.f,     0.f    };

// stream/event resources created at static-init time (host-side only).
static cudaStream_t g_s2;
static cudaEvent_t  g_ev0, g_ev1;
struct HxInitStreams {
    HxInitStreams() {
        cudaStreamCreateWithFlags(&g_s2, cudaStreamNonBlocking);
        cudaEventCreateWithFlags(&g_ev0, cudaEventDisableTiming);
        cudaEventCreateWithFlags(&g_ev1, cudaEventDisableTiming);
    }
};
static HxInitStreams g_hx_init;

__device__ __forceinline__ float dot4(float4 a, float4 b) {
    return a.x*b.x + a.y*b.y + a.z*b.z + a.w*b.w;
}

// ---------------------------------------------------------------------------
// One CTA per batch row b, 1024 threads. 16-lane groups each own one k per
// iteration; lane `pos` loads row[pos] and row[pos+16] (float4 units) so each
// group's LDG.128 covers 256B contiguous. Mainloop is guard-free (8192 negs =
// 128 iters x 64 groups exactly); the two positive k's are a warp-0 prologue.
__global__ __launch_bounds__(1024, 1) void gather_stats_kernel(
    const float* __restrict__ emb0, const float* __restrict__ emb1,
    const float* __restrict__ mem0, const float* __restrict__ mem1,
    const int* __restrict__ pos_idx, const int* __restrict__ neg_idx)
{
    const int b   = blockIdx.x;
    const int tid = threadIdx.x;
    const int w   = tid >> 5;     // warp 0..31
    const int l   = tid & 31;
    const int grp = l >> 4;       // 2 groups per warp
    const int pos = l & 15;       // lane within group == stat id == D-segment
    const int m   = pos & 7;
    const bool isB = (pos >= 8);

    const float4* e0p = (const float4*)(emb0 + b * DD);
    const float4* e1p = (const float4*)(emb1 + b * DD);
    const float4 e0a = e0p[pos], e0b = e0p[pos + 16];
    const float4 e1a = e1p[pos], e1b = e1p[pos + 16];

    const float czu = c_ZU[m], czv = c_ZV[m];
    const float cwu = c_WU[m], cwv = c_WV[m], cwc = c_WC[m];

    const int* nrow = neg_idx + b * NEGK;
    float acc = 0.f;
    const int kbase = (w << 1) + grp;   // 0..63

    // ---- prologue: warp 0 handles the two positive k's (k = grp) ----------
    if (w == 0) {
        const int k   = grp;
        const int idx = pos_idx[b * 2 + k];
        const float4* r0 = (const float4*)(mem0 + idx * DD);
        const float4* r1 = (const float4*)(mem1 + idx * DD);
        const float4 a0 = r0[pos], a1 = r0[pos + 16];
        const float4 b0 = r1[pos], b1 = r1[pos + 16];

        float pu = dot4(a0, e1a) + dot4(a1, e1b);
        float pv = dot4(b0, e0a) + dot4(b1, e0b);
        float pp = dot4(a0, e0a) + dot4(a1, e0b);
        float pq = dot4(b0, e1a) + dot4(b1, e1b);
        #pragma unroll
        for (int d = 1; d < 16; d <<= 1) {
            pu += __shfl_xor_sync(0xffffffffu, pu, d);
            pv += __shfl_xor_sync(0xffffffffu, pv, d);
            pp += __shfl_xor_sync(0xffffffffu, pp, d);
            pq += __shfl_xor_sync(0xffffffffu, pq, d);
        }
        const float u = pu * INV_TAU, v = pv * INV_TAU;
        const float p = pp * INV_TAU, q = pq * INV_TAU;
        if (pos == 0) {
            g_direct[b][k]     = u;
            g_direct[b][2 + k] = v;
            if (k == 1) { g_direct[b][4] = p; g_direct[b][5] = q; }
        }
        const float x = isB ? p : u;
        const float y = isB ? q : v;
        if (!isB || k == 1)
            acc += __expf(czu * x + czv * y) * (cwu * x + cwv * y + cwc);
    }

    // ---- mainloop: 128 guard-free iterations over the negatives -----------
    // index prefetch distance 2 hides the idx->row L2 round-trip chain.
    int i0 = __ldg(nrow + kbase);
    int i1 = __ldg(nrow + 64 + kbase);

    #pragma unroll 2
    for (int it = 0; it < 128; ++it) {
        const int idx = i0;
        i0 = i1;
        if (it < 126) i1 = __ldg(nrow + (it + 2) * 64 + kbase);

        const float4* r0 = (const float4*)(mem0 + idx * DD);
        const float4* r1 = (const float4*)(mem1 + idx * DD);
        const float4 a0 = r0[pos], a1 = r0[pos + 16];
        const float4 b0 = r1[pos], b1 = r1[pos + 16];

        float pu = dot4(a0, e1a) + dot4(a1, e1b);   // m0 . e1
        float pv = dot4(b0, e0a) + dot4(b1, e0b);   // m1 . e0
        float pp = dot4(a0, e0a) + dot4(a1, e0b);   // m0 . e0
        float pq = dot4(b0, e1a) + dot4(b1, e1b);   // m1 . e1

        #pragma unroll
        for (int d = 1; d < 16; d <<= 1) {
            pu += __shfl_xor_sync(0xffffffffu, pu, d);
            pv += __shfl_xor_sync(0xffffffffu, pv, d);
            pp += __shfl_xor_sync(0xffffffffu, pp, d);
            pq += __shfl_xor_sync(0xffffffffu, pq, d);
        }
        const float u = pu * INV_TAU, v = pv * INV_TAU;
        const float p = pp * INV_TAU, q = pq * INV_TAU;

        const float x = isB ? p : u;
        const float y = isB ? q : v;
        acc += __expf(czu * x + czv * y) * (cwu * x + cwv * y + cwc);
    }

    // combine the warp's two groups (same stat id)
    acc += __shfl_xor_sync(0xffffffffu, acc, 16);

    __shared__ float sm[16][32];
    if (l < 16) sm[l][w] = acc;
    __syncthreads();
    if (tid < 16) {
        float s = 0.f;
        #pragma unroll
        for (int ww = 0; ww < 32; ++ww) s += sm[tid][ww];
        g_rowstats[b][tid] = s;
    }
}

// ---------------------------------------------------------------------------
// Streaming copy of mem0|mem1 into out (evict-first both sides so the
// concurrent gather keeps its L2-resident working set).
__global__ __launch_bounds__(256) void copy_mems_kernel(
    const float4* __restrict__ m0, const float4* __restrict__ m1,
    float4* __restrict__ dst)
{
    const int n = NPTS * DD / 4;
    const int stride = gridDim.x * blockDim.x;
    for (int i = blockIdx.x * blockDim.x + threadIdx.x; i < n; i += stride) {
        __stcs(dst + i,     __ldcs(m0 + i));
        __stcs(dst + n + i, __ldcs(m1 + i));
    }
}

// one warp per (b, net): momentum update + renorm + scatter (exact fp32).
__global__ void update_rows_kernel(
    const float* __restrict__ emb0, const float* __restrict__ emb1,
    const float* __restrict__ mem0, const float* __restrict__ mem1,
    const int* __restrict__ pos_idx, float* __restrict__ out)
{
    const int g = blockIdx.x * (blockDim.x >> 5) + (threadIdx.x >> 5);
    const int l = threadIdx.x & 31;
    if (g >= 2 * BB) return;
    const int b = g >> 1, net = g & 1;
    const float* mem = net ? mem1 : mem0;
    const float* emb = net ? emb1 : emb0;
    const int p0 = pos_idx[b * 2];

    float4 mv = ((const float4*)(mem + (size_t)p0 * DD))[l];
    float4 ev = ((const float4*)(emb + (size_t)b  * DD))[l];
    float4 u;
    u.x = 0.5f * (mv.x + ev.x);  u.y = 0.5f * (mv.y + ev.y);
    u.z = 0.5f * (mv.z + ev.z);  u.w = 0.5f * (mv.w + ev.w);
    float ss = u.x*u.x + u.y*u.y + u.z*u.z + u.w*u.w;
    #pragma unroll
    for (int d = 1; d < 32; d <<= 1) ss += __shfl_xor_sync(0xffffffffu, ss, d);
    const float r = 1.0f / sqrtf(ss);
    u.x *= r; u.y *= r; u.z *= r; u.w *= r;

    float* dst = out + 4 + (size_t)net * NPTS * DD + (size_t)p0 * DD;
    ((float4*)dst)[l] = u;
}

// ---------------------------------------------------------------------------
__global__ void finalize_kernel(float* __restrict__ out)
{
    const int b = threadIdx.x;   // 128 threads
    const float* st = g_rowstats[b];
    const float* dv = g_direct[b];

    const float s1u = st[0],  s1v = st[1],  s3u = st[2],  wuu = st[3];
    const float wuv = st[4],  s3v = st[5],  wvv = st[6],  wvu = st[7];
    const float s1p = st[8],  s1q = st[9],  s3p = st[10], wpp = st[11];
    const float wpq = st[12], s3q = st[13], wqq = st[14], wqp = st[15];
    const float u0 = dv[0], u1 = dv[1], v0 = dv[2], v1 = dv[3];
    const float p1 = dv[4], q1 = dv[5];

    const float icl_b = -((u0 + u1) * 0.5f - logf(s1u))
                        -((v0 + v1) * 0.5f - logf(s1v));
    const float vcl_b = -(p1 - logf(s1p)) - (q1 - logf(s1q));
    const float l3u = logf(s3u), l3v = logf(s3v);
    const float l3p = logf(s3p), l3q = logf(s3q);
    const float sicl_b = ((wvv - wvu) / s3v - l3v + l3u)
                       + ((wuu - wuv) / s3u - l3u + l3v);
    const float svcl_b = ((wqq - wqp) / s3q - l3q + l3p)
                       + ((wpp - wpq) / s3p - l3p + l3q);

    __shared__ float red[4][4];
    float vals[4] = {vcl_b, svcl_b, icl_b, sicl_b};
    const int w = b >> 5, l = b & 31;
    #pragma unroll
    for (int i = 0; i < 4; ++i) {
        float s = vals[i];
        #pragma unroll
        for (int d = 1; d < 32; d <<= 1) s += __shfl_xor_sync(0xffffffffu, s, d);
        if (l == 0) red[i][w] = s;
    }
    __syncthreads();
    if (b == 0) {
        out[0] = (red[0][0] + red[0][1] + red[0][2] + red[0][3]) * (1.0f / BB);
        out[1] = (red[1][0] + red[1][1] + red[1][2] + red[1][3]) * (9.0f / BB);
        out[2] = (red[2][0] + red[2][1] + red[2][2] + red[2][3]) * (1.0f / BB);
        out[3] = (red[3][0] + red[3][1] + red[3][2] + red[3][3]) * (9.0f / BB);
    }
}

extern "C" void kernel_launch(void* const* d_in, const int* in_sizes, int n_in,
                              void* d_out, int out_size)
{
    const float* emb0    = (const float*)d_in[0];
    const float* emb1    = (const float*)d_in[1];
    const float* mem0    = (const float*)d_in[2];
    const float* mem1    = (const float*)d_in[3];
    const int*   pos_idx = (const int*)d_in[4];
    const int*   neg_idx = (const int*)d_in[5];
    float* out = (float*)d_out;

    cudaEventRecord(g_ev0, 0);
    cudaStreamWaitEvent(g_s2, g_ev0, 0);

    // branch B: DRAM-bound copy + exact scatter update (overlaps the gather)
    copy_mems_kernel<<<2048, 256, 0, g_s2>>>(
        (const float4*)mem0, (const float4*)mem1, (float4*)(out + 4));
    update_rows_kernel<<<8, 1024, 0, g_s2>>>(emb0, emb1, mem0, mem1, pos_idx, out);
    cudaEventRecord(g_ev1, g_s2);

    // branch A (critical path): pipelined fp32 gather -> finalize
    gather_stats_kernel<<<BB, 1024>>>(emb0, emb1, mem0, mem1, pos_idx, neg_idx);
    finalize_kernel<<<1, 128>>>(out);

    cudaStreamWaitEvent(0, g_ev1, 0);
}